// round 2
// baseline (speedup 1.0000x reference)
#include <cuda_runtime.h>

#define BB 4
#define NN 512
#define MM 512
#define DD 128
#define TILE 64

// ---------------- device scratch (no allocations allowed) ----------------
__device__ float g_z[BB * NN * MM];      // 4 MB pairwise L1 distances
__device__ float g_rmin[BB * NN];        // per-row min z (valid cols)
__device__ float g_rinv[BB * NN];        // 1 / row softmax denom
__device__ float g_cmin[BB * MM];        // per-col min z (valid rows)
__device__ float g_cinv[BB * MM];        // 1 / col softmax denom
__device__ float g_pnum[BB * NN];        // per-row partial numerator
__device__ float g_pden[BB * NN];        // per-row partial denominator

// Length buffers may be int32 (jax canonicalizes int64->int32 without x64) or
// genuine int64. Sniff the layout: for int64 the high word of the first 8 bytes
// is 0; for int32 it is lengths[1] in [64,512] != 0. Safe reads either way.
__device__ __forceinline__ int load_len(const void* p, int i) {
    const unsigned* u = (const unsigned*)p;
    if (u[1] == 0u) {                       // int64 layout
        return (int)((const long long*)p)[i];
    }
    return ((const int*)p)[i];              // int32 layout
}

// ---------------- kernel 1: pairwise L1 distance, tiled ----------------
// Grid (8, 8, 4); 256 threads; 64x64 tile, 4x4 register blocking.
// Shared layout is transposed [d][row] so the inner loop does two LDS.128
// (x broadcast across tx, y consecutive across tx -> conflict-free).
__global__ __launch_bounds__(256) void k_zdiff(
    const float* __restrict__ x, const float* __restrict__ y,
    const void* __restrict__ xlen, const void* __restrict__ ylen) {
    int b = blockIdx.z;
    int n0 = blockIdx.y * TILE;
    int m0 = blockIdx.x * TILE;
    int xl = load_len(xlen, b);
    int yl = load_len(ylen, b);
    if (n0 >= xl || m0 >= yl) return;   // tile fully masked -> skip

    __shared__ float xs[64 * 64];   // [d][n], d-phase of 64
    __shared__ float ys[64 * 64];   // [d][m]

    int tid = threadIdx.x;
    int ty = tid >> 4;      // 0..15 -> n sub-block
    int tx = tid & 15;      // 0..15 -> m sub-block

    const float* xb = x + ((size_t)b * NN + n0) * DD;
    const float* yb = y + ((size_t)b * MM + m0) * DD;

    float acc[4][4];
#pragma unroll
    for (int i = 0; i < 4; i++)
#pragma unroll
        for (int j = 0; j < 4; j++) acc[i][j] = 0.0f;

#pragma unroll
    for (int p = 0; p < 2; p++) {
        // load 64 rows x 64 d, transposed into smem
#pragma unroll
        for (int it = 0; it < 4; it++) {
            int idx = tid + 256 * it;
            int n  = idx & 63;
            int dq = idx >> 6;          // 0..15
            const float4 vx = *(const float4*)(xb + (size_t)n * DD + p * 64 + dq * 4);
            const float4 vy = *(const float4*)(yb + (size_t)n * DD + p * 64 + dq * 4);
            xs[(dq * 4 + 0) * 64 + n] = vx.x;
            xs[(dq * 4 + 1) * 64 + n] = vx.y;
            xs[(dq * 4 + 2) * 64 + n] = vx.z;
            xs[(dq * 4 + 3) * 64 + n] = vx.w;
            ys[(dq * 4 + 0) * 64 + n] = vy.x;
            ys[(dq * 4 + 1) * 64 + n] = vy.y;
            ys[(dq * 4 + 2) * 64 + n] = vy.z;
            ys[(dq * 4 + 3) * 64 + n] = vy.w;
        }
        __syncthreads();

#pragma unroll 8
        for (int d = 0; d < 64; d++) {
            float4 lx = *(const float4*)(xs + d * 64 + ty * 4);
            float4 ly = *(const float4*)(ys + d * 64 + tx * 4);
            float xa[4] = {lx.x, lx.y, lx.z, lx.w};
            float ya[4] = {ly.x, ly.y, ly.z, ly.w};
#pragma unroll
            for (int i = 0; i < 4; i++)
#pragma unroll
                for (int j = 0; j < 4; j++)
                    acc[i][j] += fabsf(xa[i] - ya[j]);
        }
        __syncthreads();
    }

    float* zb = g_z + ((size_t)b * NN + n0 + ty * 4) * MM + m0 + tx * 4;
#pragma unroll
    for (int i = 0; i < 4; i++) {
        float4 v = make_float4(acc[i][0], acc[i][1], acc[i][2], acc[i][3]);
        *(float4*)(zb + (size_t)i * MM) = v;
    }
}

// ---------------- kernel 2: row stats (softmax over m / beta denom) ------
// One warp per (b, n). Deterministic: fixed-stride per-lane loop + butterfly.
__global__ __launch_bounds__(256) void k_rowstats(
    const void* __restrict__ xlen, const void* __restrict__ ylen) {
    int gw = (blockIdx.x * 256 + threadIdx.x) >> 5;
    int lane = threadIdx.x & 31;
    int b = gw >> 9;
    int n = gw & (NN - 1);
    int xl = load_len(xlen, b);
    int yl = load_len(ylen, b);
    if (n >= xl) return;

    const float* zr = g_z + ((size_t)b * NN + n) * MM;
    float zmin = 3.0e38f;
    for (int m = lane; m < yl; m += 32) zmin = fminf(zmin, zr[m]);
#pragma unroll
    for (int o = 16; o; o >>= 1) zmin = fminf(zmin, __shfl_xor_sync(0xffffffffu, zmin, o));

    float s = 0.0f;
    for (int m = lane; m < yl; m += 32) s += __expf(zmin - zr[m]);
#pragma unroll
    for (int o = 16; o; o >>= 1) s += __shfl_xor_sync(0xffffffffu, s, o);

    if (lane == 0) {
        g_rmin[b * NN + n] = zmin;
        g_rinv[b * NN + n] = 1.0f / s;
    }
}

// ---------------- kernel 3: col stats (softmax over n / alpha denom) -----
// Block handles 32 columns, 8-way n-parallel; coalesced reads; fixed-order reduce.
__global__ __launch_bounds__(256) void k_colstats(
    const void* __restrict__ xlen, const void* __restrict__ ylen) {
    int blk = blockIdx.x;           // 0..63
    int b  = blk >> 4;
    int m0 = (blk & 15) * 32;
    int xl = load_len(xlen, b);
    int yl = load_len(ylen, b);
    if (m0 >= yl) return;

    int tx = threadIdx.x & 31;      // column within group
    int tg = threadIdx.x >> 5;      // 0..7, n-partition
    int m = m0 + tx;
    const float* zc = g_z + (size_t)b * NN * MM;

    __shared__ float red[8][32];

    float zmin = 3.0e38f;
    for (int n = tg; n < xl; n += 8) zmin = fminf(zmin, zc[(size_t)n * MM + m]);
    red[tg][tx] = zmin;
    __syncthreads();
    if (tg == 0) {
        float cm = red[0][tx];
#pragma unroll
        for (int r = 1; r < 8; r++) cm = fminf(cm, red[r][tx]);
        red[0][tx] = cm;
    }
    __syncthreads();
    float cm = red[0][tx];
    __syncthreads();

    float s = 0.0f;
    for (int n = tg; n < xl; n += 8) s += __expf(cm - zc[(size_t)n * MM + m]);
    red[tg][tx] = s;
    __syncthreads();
    if (tg == 0) {
        float t = red[0][tx];
#pragma unroll
        for (int r = 1; r < 8; r++) t += red[r][tx];
        g_cmin[b * MM + m] = cm;
        g_cinv[b * MM + m] = 1.0f / t;
    }
}

// ---------------- kernel 4: combine alpha/beta, per-row partials ---------
__global__ __launch_bounds__(256) void k_accum(
    const void* __restrict__ xlen, const void* __restrict__ ylen) {
    int gw = (blockIdx.x * 256 + threadIdx.x) >> 5;
    int lane = threadIdx.x & 31;
    int b = gw >> 9;
    int n = gw & (NN - 1);
    int xl = load_len(xlen, b);
    int yl = load_len(ylen, b);
    if (n >= xl) return;

    const float* zr   = g_z    + ((size_t)b * NN + n) * MM;
    const float* cmin = g_cmin + b * MM;
    const float* cinv = g_cinv + b * MM;
    float rmin = g_rmin[b * NN + n];
    float rinv = g_rinv[b * NN + n];

    float num = 0.0f, den = 0.0f;
    for (int m = lane; m < yl; m += 32) {
        float z = zr[m];
        float beta  = __expf(rmin - z) * rinv;
        float alpha = __expf(cmin[m] - z) * cinv[m];
        float a = alpha + beta - alpha * beta;
        den += a;
        num += a * z;
    }
#pragma unroll
    for (int o = 16; o; o >>= 1) {
        num += __shfl_xor_sync(0xffffffffu, num, o);
        den += __shfl_xor_sync(0xffffffffu, den, o);
    }
    if (lane == 0) {
        g_pnum[b * NN + n] = num;
        g_pden[b * NN + n] = den;
    }
}

// ---------------- kernel 5: final deterministic reduction ----------------
__global__ __launch_bounds__(256) void k_final(
    const void* __restrict__ xlen, float* __restrict__ out) {
    int b = blockIdx.x;
    int xl = load_len(xlen, b);
    int tid = threadIdx.x;

    float num = 0.0f, den = 0.0f;
    for (int n = tid; n < xl; n += 256) {
        num += g_pnum[b * NN + n];
        den += g_pden[b * NN + n];
    }
    __shared__ float sn[256];
    __shared__ float sd[256];
    sn[tid] = num;
    sd[tid] = den;
    __syncthreads();
    for (int s2 = 128; s2; s2 >>= 1) {
        if (tid < s2) {
            sn[tid] += sn[tid + s2];
            sd[tid] += sd[tid + s2];
        }
        __syncthreads();
    }
    if (tid == 0) out[b] = -sn[0] / sd[0];
}

// ---------------- launch ----------------
extern "C" void kernel_launch(void* const* d_in, const int* in_sizes, int n_in,
                              void* d_out, int out_size) {
    const float* x = (const float*)d_in[0];
    const float* y = (const float*)d_in[1];
    const void* xl = d_in[2];
    const void* yl = d_in[3];
    float* out = (float*)d_out;

    dim3 g1(MM / TILE, NN / TILE, BB);          // (8, 8, 4)
    k_zdiff<<<g1, 256>>>(x, y, xl, yl);
    k_rowstats<<<BB * NN / 8, 256>>>(xl, yl);   // 256 blocks
    k_colstats<<<BB * (MM / 32), 256>>>(xl, yl); // 64 blocks
    k_accum<<<BB * NN / 8, 256>>>(xl, yl);      // 256 blocks
    k_final<<<BB, 256>>>(xl, out);
}

// round 3
// speedup vs baseline: 1.4774x; 1.4774x over previous
#include <cuda_runtime.h>

#define BB 4
#define NN 512
#define MM 512
#define DD 128
#define TILE 64

typedef unsigned long long u64;

// ---------------- device scratch (no allocations allowed) ----------------
__device__ float g_z[BB * NN * MM];      // 4 MB pairwise L1 distances
__device__ float g_rmin[BB * NN];        // per-row min z (valid cols)
__device__ float g_rinv[BB * NN];        // 1 / row softmax denom
__device__ float g_cmin[BB * MM];        // per-col min z (valid rows)
__device__ float g_cinv[BB * MM];        // 1 / col softmax denom
__device__ float g_pnum[BB * NN];        // per-row partial numerator
__device__ float g_pden[BB * NN];        // per-row partial denominator
__device__ int   g_cnt[BB];              // last-block-done counters

// Length buffers may be int32 (jax canonicalizes int64->int32 without x64) or
// genuine int64. Sniff: for int64 the high word of the first 8 bytes is 0.
__device__ __forceinline__ int load_len(const void* p, int i) {
    const unsigned* u = (const unsigned*)p;
    if (u[1] == 0u) return (int)((const long long*)p)[i];
    return ((const int*)p)[i];
}

// ---------------- packed f32x2 helpers (Blackwell) ----------------
__device__ __forceinline__ u64 pk2(float lo, float hi) {
    u64 r; asm("mov.b64 %0, {%1, %2};" : "=l"(r) : "f"(lo), "f"(hi)); return r;
}
__device__ __forceinline__ u64 add2(u64 a, u64 b) {
    u64 r; asm("add.rn.f32x2 %0, %1, %2;" : "=l"(r) : "l"(a), "l"(b)); return r;
}
__device__ __forceinline__ void upk2(u64 v, float& lo, float& hi) {
    asm("mov.b64 {%0, %1}, %2;" : "=f"(lo), "=f"(hi) : "l"(v));
}

// ---------------- kernel 1: pairwise L1 distance, tiled ----------------
// Grid (8, 8, 4); 256 threads; 64x64 tile, 4x4 register blocking.
// y is staged NEGATED in smem; inner loop is packed f32x2: add2(x, -y),
// 64-bit AND for abs (alu pipe), add2 accumulate. Halves fma-pipe work.
__global__ __launch_bounds__(256) void k_zdiff(
    const float* __restrict__ x, const float* __restrict__ y,
    const void* __restrict__ xlen, const void* __restrict__ ylen) {
    // reset last-block counters for this launch (before any early return)
    if (blockIdx.x == 0 && blockIdx.y == 0 && blockIdx.z == 0 && threadIdx.x < BB)
        g_cnt[threadIdx.x] = 0;

    int b = blockIdx.z;
    int n0 = blockIdx.y * TILE;
    int m0 = blockIdx.x * TILE;
    int xl = load_len(xlen, b);
    int yl = load_len(ylen, b);
    if (n0 >= xl || m0 >= yl) return;   // tile fully masked -> skip

    __shared__ float xs[64 * 64];   // [d][n], d-phase of 64
    __shared__ float ys[64 * 64];   // [d][m], NEGATED y

    int tid = threadIdx.x;
    int ty = tid >> 4;      // 0..15 -> n sub-block
    int tx = tid & 15;      // 0..15 -> m sub-block

    const float* xb = x + ((size_t)b * NN + n0) * DD;
    const float* yb = y + ((size_t)b * MM + m0) * DD;

    u64 acc2[4][2];
#pragma unroll
    for (int i = 0; i < 4; i++) { acc2[i][0] = 0ull; acc2[i][1] = 0ull; }

    const u64 ABSM = 0x7FFFFFFF7FFFFFFFull;

#pragma unroll
    for (int p = 0; p < 2; p++) {
        // load 64 rows x 64 d, transposed into smem (y negated)
#pragma unroll
        for (int it = 0; it < 4; it++) {
            int idx = tid + 256 * it;
            int n  = idx & 63;
            int dq = idx >> 6;          // 0..15
            const float4 vx = *(const float4*)(xb + (size_t)n * DD + p * 64 + dq * 4);
            const float4 vy = *(const float4*)(yb + (size_t)n * DD + p * 64 + dq * 4);
            xs[(dq * 4 + 0) * 64 + n] = vx.x;
            xs[(dq * 4 + 1) * 64 + n] = vx.y;
            xs[(dq * 4 + 2) * 64 + n] = vx.z;
            xs[(dq * 4 + 3) * 64 + n] = vx.w;
            ys[(dq * 4 + 0) * 64 + n] = -vy.x;
            ys[(dq * 4 + 1) * 64 + n] = -vy.y;
            ys[(dq * 4 + 2) * 64 + n] = -vy.z;
            ys[(dq * 4 + 3) * 64 + n] = -vy.w;
        }
        __syncthreads();

#pragma unroll 8
        for (int d = 0; d < 64; d++) {
            float4 lx = *(const float4*)(xs + d * 64 + ty * 4);
            float4 ln = *(const float4*)(ys + d * 64 + tx * 4);
            u64 ny0 = pk2(ln.x, ln.y);
            u64 ny1 = pk2(ln.z, ln.w);
            float xa[4] = {lx.x, lx.y, lx.z, lx.w};
#pragma unroll
            for (int i = 0; i < 4; i++) {
                u64 xx = pk2(xa[i], xa[i]);
                u64 t0 = add2(xx, ny0) & ABSM;
                u64 t1 = add2(xx, ny1) & ABSM;
                acc2[i][0] = add2(acc2[i][0], t0);
                acc2[i][1] = add2(acc2[i][1], t1);
            }
        }
        __syncthreads();
    }

    float* zb = g_z + ((size_t)b * NN + n0 + ty * 4) * MM + m0 + tx * 4;
#pragma unroll
    for (int i = 0; i < 4; i++) {
        float4 v;
        upk2(acc2[i][0], v.x, v.y);
        upk2(acc2[i][1], v.z, v.w);
        *(float4*)(zb + (size_t)i * MM) = v;
    }
}

// ---------------- kernel 2: fused row + col softmax stats ----------------
// Grid 192 blocks x 512 threads.
//   blocks [0,128): row stats. 16 warps/block, one (b,n) row per warp,
//                   float4 loads + unroll-4 for MLP.
//   blocks [128,192): col stats. 32 columns/block, 16-way n-partition,
//                   coalesced loads, manual unroll-4, fixed-order reduce.
__global__ __launch_bounds__(512) void k_stats(
    const void* __restrict__ xlen, const void* __restrict__ ylen) {
    int blk = blockIdx.x;
    int tid = threadIdx.x;

    if (blk < 128) {
        // ---- row stats ----
        int lane = tid & 31;
        int wid  = tid >> 5;
        int b = blk >> 5;
        int n = (blk & 31) * 16 + wid;
        int xl = load_len(xlen, b);
        int yl = load_len(ylen, b);
        if (n >= xl) return;

        const float*  zr = g_z + ((size_t)b * NN + n) * MM;
        const float4* z4 = (const float4*)zr;
        int nv4 = yl >> 2;
        int base = yl & ~3;

        float zmin = 3.0e38f;
#pragma unroll 4
        for (int i = lane; i < nv4; i += 32) {
            float4 v = z4[i];
            zmin = fminf(zmin, fminf(fminf(v.x, v.y), fminf(v.z, v.w)));
        }
        if (base + lane < yl) zmin = fminf(zmin, zr[base + lane]);
#pragma unroll
        for (int o = 16; o; o >>= 1) zmin = fminf(zmin, __shfl_xor_sync(0xffffffffu, zmin, o));

        float s = 0.0f;
#pragma unroll 4
        for (int i = lane; i < nv4; i += 32) {
            float4 v = z4[i];
            s += __expf(zmin - v.x) + __expf(zmin - v.y)
               + __expf(zmin - v.z) + __expf(zmin - v.w);
        }
        if (base + lane < yl) s += __expf(zmin - zr[base + lane]);
#pragma unroll
        for (int o = 16; o; o >>= 1) s += __shfl_xor_sync(0xffffffffu, s, o);

        if (lane == 0) {
            g_rmin[b * NN + n] = zmin;
            g_rinv[b * NN + n] = 1.0f / s;
        }
    } else {
        // ---- col stats ----
        int cblk = blk - 128;           // 0..63
        int b  = cblk >> 4;
        int m0 = (cblk & 15) * 32;
        int xl = load_len(xlen, b);
        int yl = load_len(ylen, b);
        if (m0 >= yl) return;

        int tx = tid & 31;      // column within group
        int tg = tid >> 5;      // 0..15, n-partition
        int m = m0 + tx;
        const float* zc = g_z + (size_t)b * NN * MM + m;

        __shared__ float red[16][32];

        float zmin = 3.0e38f;
        int n = tg;
        for (; n + 48 < xl; n += 64) {
            float a0 = zc[(size_t)(n     ) * MM];
            float a1 = zc[(size_t)(n + 16) * MM];
            float a2 = zc[(size_t)(n + 32) * MM];
            float a3 = zc[(size_t)(n + 48) * MM];
            zmin = fminf(zmin, fminf(fminf(a0, a1), fminf(a2, a3)));
        }
        for (; n < xl; n += 16) zmin = fminf(zmin, zc[(size_t)n * MM]);
        red[tg][tx] = zmin;
        __syncthreads();
        if (tg == 0) {
            float cm = red[0][tx];
#pragma unroll
            for (int r = 1; r < 16; r++) cm = fminf(cm, red[r][tx]);
            red[0][tx] = cm;
        }
        __syncthreads();
        float cm = red[0][tx];
        __syncthreads();

        float s = 0.0f;
        n = tg;
        for (; n + 48 < xl; n += 64) {
            float a0 = zc[(size_t)(n     ) * MM];
            float a1 = zc[(size_t)(n + 16) * MM];
            float a2 = zc[(size_t)(n + 32) * MM];
            float a3 = zc[(size_t)(n + 48) * MM];
            s += __expf(cm - a0) + __expf(cm - a1) + __expf(cm - a2) + __expf(cm - a3);
        }
        for (; n < xl; n += 16) s += __expf(cm - zc[(size_t)n * MM]);
        red[tg][tx] = s;
        __syncthreads();
        if (tg == 0) {
            float t = red[0][tx];
#pragma unroll
            for (int r = 1; r < 16; r++) t += red[r][tx];
            g_cmin[b * MM + m] = cm;
            g_cinv[b * MM + m] = 1.0f / t;
        }
    }
}

// ---------------- kernel 3: combine + fused final reduction --------------
// 128 blocks x 512 threads; 16 warps/block, one (b,n) row per warp.
// float4 loads for z / cmin / cinv. Last block per batch (deterministic
// counter) does the fixed-order final reduce for that batch.
__global__ __launch_bounds__(512) void k_accum(
    const void* __restrict__ xlen, const void* __restrict__ ylen,
    float* __restrict__ out) {
    int blk = blockIdx.x;
    int tid = threadIdx.x;
    int lane = tid & 31;
    int wid  = tid >> 5;
    int b = blk >> 5;
    int n = (blk & 31) * 16 + wid;
    int xl = load_len(xlen, b);
    int yl = load_len(ylen, b);

    if (n < xl) {
        const float*  zr  = g_z + ((size_t)b * NN + n) * MM;
        const float4* z4  = (const float4*)zr;
        const float*  cmn = g_cmin + b * MM;
        const float*  civ = g_cinv + b * MM;
        const float4* cm4 = (const float4*)cmn;
        const float4* ci4 = (const float4*)civ;
        float rmin = g_rmin[b * NN + n];
        float rinv = g_rinv[b * NN + n];

        int nv4 = yl >> 2;
        int base = yl & ~3;

        float num = 0.0f, den = 0.0f;
#pragma unroll 2
        for (int i = lane; i < nv4; i += 32) {
            float4 z = z4[i];
            float4 cm = cm4[i];
            float4 ci = ci4[i];
            {
                float beta  = __expf(rmin - z.x) * rinv;
                float alpha = __expf(cm.x - z.x) * ci.x;
                float a = alpha + beta - alpha * beta;
                den += a; num += a * z.x;
            }
            {
                float beta  = __expf(rmin - z.y) * rinv;
                float alpha = __expf(cm.y - z.y) * ci.y;
                float a = alpha + beta - alpha * beta;
                den += a; num += a * z.y;
            }
            {
                float beta  = __expf(rmin - z.z) * rinv;
                float alpha = __expf(cm.z - z.z) * ci.z;
                float a = alpha + beta - alpha * beta;
                den += a; num += a * z.z;
            }
            {
                float beta  = __expf(rmin - z.w) * rinv;
                float alpha = __expf(cm.w - z.w) * ci.w;
                float a = alpha + beta - alpha * beta;
                den += a; num += a * z.w;
            }
        }
        if (base + lane < yl) {
            int m = base + lane;
            float z = zr[m];
            float beta  = __expf(rmin - z) * rinv;
            float alpha = __expf(cmn[m] - z) * civ[m];
            float a = alpha + beta - alpha * beta;
            den += a; num += a * z;
        }
#pragma unroll
        for (int o = 16; o; o >>= 1) {
            num += __shfl_xor_sync(0xffffffffu, num, o);
            den += __shfl_xor_sync(0xffffffffu, den, o);
        }
        if (lane == 0) {
            g_pnum[b * NN + n] = num;
            g_pden[b * NN + n] = den;
        }
    }

    // ---- last-block-done: fused final reduction (deterministic) ----
    __shared__ int s_last;
    __syncthreads();
    if (tid == 0) {
        __threadfence();
        int old = atomicAdd(&g_cnt[b], 1);
        s_last = (old == 31);
    }
    __syncthreads();
    if (!s_last) return;
    __threadfence();

    float num = 0.0f, den = 0.0f;
    for (int i = tid; i < xl; i += 512) {
        num += g_pnum[b * NN + i];
        den += g_pden[b * NN + i];
    }
    __shared__ float sn[512];
    __shared__ float sd[512];
    sn[tid] = num;
    sd[tid] = den;
    __syncthreads();
    for (int s2 = 256; s2; s2 >>= 1) {
        if (tid < s2) {
            sn[tid] += sn[tid + s2];
            sd[tid] += sd[tid + s2];
        }
        __syncthreads();
    }
    if (tid == 0) out[b] = -sn[0] / sd[0];
}

// ---------------- launch ----------------
extern "C" void kernel_launch(void* const* d_in, const int* in_sizes, int n_in,
                              void* d_out, int out_size) {
    const float* x = (const float*)d_in[0];
    const float* y = (const float*)d_in[1];
    const void* xl = d_in[2];
    const void* yl = d_in[3];
    float* out = (float*)d_out;

    dim3 g1(MM / TILE, NN / TILE, BB);          // (8, 8, 4)
    k_zdiff<<<g1, 256>>>(x, y, xl, yl);
    k_stats<<<192, 512>>>(xl, yl);
    k_accum<<<128, 512>>>(xl, yl, out);
}

// round 4
// speedup vs baseline: 1.4932x; 1.0107x over previous
#include <cuda_runtime.h>

#define BB 4
#define NN 512
#define MM 512
#define DD 128
#define TN 64
#define TM 32

typedef unsigned long long u64;

// ---------------- device scratch (no allocations allowed) ----------------
__device__ float g_z[BB * NN * MM];      // 4 MB pairwise L1 distances
__device__ float g_rmin[BB * NN];        // per-row min z (valid cols)
__device__ float g_rinv[BB * NN];        // 1 / row softmax denom
__device__ float g_cmin[BB * MM];        // per-col min z (valid rows)
__device__ float g_cinv[BB * MM];        // 1 / col softmax denom
__device__ float g_pnum[BB * NN];        // per-row partial numerator
__device__ float g_pden[BB * NN];        // per-row partial denominator
__device__ int   g_cnt[BB];              // last-block-done counters

// Length buffers may be int32 (jax canonicalizes int64->int32 without x64) or
// genuine int64. Sniff: for int64 the high word of the first 8 bytes is 0.
__device__ __forceinline__ int load_len(const void* p, int i) {
    const unsigned* u = (const unsigned*)p;
    if (u[1] == 0u) return (int)((const long long*)p)[i];
    return ((const int*)p)[i];
}

// ---------------- packed f32x2 helpers (Blackwell) ----------------
__device__ __forceinline__ u64 pk2(float lo, float hi) {
    u64 r; asm("mov.b64 %0, {%1, %2};" : "=l"(r) : "f"(lo), "f"(hi)); return r;
}
__device__ __forceinline__ u64 add2(u64 a, u64 b) {
    u64 r; asm("add.rn.f32x2 %0, %1, %2;" : "=l"(r) : "l"(a), "l"(b)); return r;
}
__device__ __forceinline__ void upk2(u64 v, float& lo, float& hi) {
    asm("mov.b64 {%0, %1}, %2;" : "=f"(lo), "=f"(hi) : "l"(v));
}

// ---------------- kernel 1: pairwise L1 distance, tiled ----------------
// Grid (16, 8, 4) = 512 blocks; 256 threads; 64x32 tile, 4n x 2m micro.
// Accumulators are n-packed u64s: the LDS.128 of xs yields n-pairs directly
// (no packing movs); y is staged negated, duplicated with 2 movs per (d,m2).
// Inner loop per d: 2 LDS + 2 MOV + 4 FADD2 + 8 LOP3 + 4 FADD2 = 20 issues
// for 8 pair-results.
__global__ __launch_bounds__(256) void k_zdiff(
    const float* __restrict__ x, const float* __restrict__ y,
    const void* __restrict__ xlen, const void* __restrict__ ylen) {
    // reset last-block counters for this launch (before any early return)
    if (blockIdx.x == 0 && blockIdx.y == 0 && blockIdx.z == 0 && threadIdx.x < BB)
        g_cnt[threadIdx.x] = 0;

    int b = blockIdx.z;
    int n0 = blockIdx.y * TN;
    int m0 = blockIdx.x * TM;
    int xl = load_len(xlen, b);
    int yl = load_len(ylen, b);
    if (n0 >= xl || m0 >= yl) return;   // tile fully masked -> skip

    __shared__ float xs[64 * TN];   // [d][n], d-phase of 64
    __shared__ float ys[64 * TM];   // [d][m], NEGATED y

    int tid = threadIdx.x;
    int ty = tid >> 4;      // 0..15 -> n micro-group (4 rows)
    int tx = tid & 15;      // 0..15 -> m micro-group (2 cols)

    const float* xb = x + ((size_t)b * NN + n0) * DD;
    const float* yb = y + ((size_t)b * MM + m0) * DD;

    u64 acc[2][2];          // [n-pair][m]
    acc[0][0] = acc[0][1] = acc[1][0] = acc[1][1] = 0ull;

    const u64 ABSM = 0x7FFFFFFF7FFFFFFFull;

#pragma unroll
    for (int p = 0; p < 2; p++) {
        // stage x: 64 n x 64 d transposed
#pragma unroll
        for (int it = 0; it < 4; it++) {
            int idx = tid + 256 * it;           // 0..1023
            int n  = idx & 63;
            int dq = idx >> 6;                  // 0..15
            const float4 vx = *(const float4*)(xb + (size_t)n * DD + p * 64 + dq * 4);
            xs[(dq * 4 + 0) * TN + n] = vx.x;
            xs[(dq * 4 + 1) * TN + n] = vx.y;
            xs[(dq * 4 + 2) * TN + n] = vx.z;
            xs[(dq * 4 + 3) * TN + n] = vx.w;
        }
        // stage y negated: 32 m x 64 d transposed
#pragma unroll
        for (int it = 0; it < 2; it++) {
            int idx = tid + 256 * it;           // 0..511
            int m  = idx & 31;
            int dq = idx >> 5;                  // 0..15
            const float4 vy = *(const float4*)(yb + (size_t)m * DD + p * 64 + dq * 4);
            ys[(dq * 4 + 0) * TM + m] = -vy.x;
            ys[(dq * 4 + 1) * TM + m] = -vy.y;
            ys[(dq * 4 + 2) * TM + m] = -vy.z;
            ys[(dq * 4 + 3) * TM + m] = -vy.w;
        }
        __syncthreads();

#pragma unroll 8
        for (int d = 0; d < 64; d++) {
            ulonglong2 lx = *(const ulonglong2*)(xs + d * TN + ty * 4);  // (n0,n1),(n2,n3)
            float2 ln = *(const float2*)(ys + d * TM + tx * 2);          // -y[m0], -y[m1]
            u64 d0 = pk2(ln.x, ln.x);
            u64 d1 = pk2(ln.y, ln.y);
            u64 t00 = add2(lx.x, d0) & ABSM;
            u64 t10 = add2(lx.y, d0) & ABSM;
            u64 t01 = add2(lx.x, d1) & ABSM;
            u64 t11 = add2(lx.y, d1) & ABSM;
            acc[0][0] = add2(acc[0][0], t00);
            acc[1][0] = add2(acc[1][0], t10);
            acc[0][1] = add2(acc[0][1], t01);
            acc[1][1] = add2(acc[1][1], t11);
        }
        __syncthreads();
    }

    // store: rows n0+ty*4+{0..3}, cols m0+tx*2+{0,1}
    float a00l, a00h, a01l, a01h, a10l, a10h, a11l, a11h;
    upk2(acc[0][0], a00l, a00h);    // z[n+0][m], z[n+1][m]
    upk2(acc[0][1], a01l, a01h);    // z[n+0][m+1], z[n+1][m+1]
    upk2(acc[1][0], a10l, a10h);    // z[n+2][m], z[n+3][m]
    upk2(acc[1][1], a11l, a11h);    // z[n+2][m+1], z[n+3][m+1]
    float* zb = g_z + ((size_t)b * NN + n0 + ty * 4) * MM + m0 + tx * 2;
    *(float2*)(zb + 0 * MM) = make_float2(a00l, a01l);
    *(float2*)(zb + 1 * MM) = make_float2(a00h, a01h);
    *(float2*)(zb + 2 * MM) = make_float2(a10l, a11l);
    *(float2*)(zb + 3 * MM) = make_float2(a10h, a11h);
}

// ---------------- kernel 2: fused row + col softmax stats ----------------
// 320 blocks x 256 threads.
//   blocks [0,256): row stats. 8 warps/block, one (b,n) row per warp.
//   blocks [256,320): col stats. 32 columns/block, 8-way n-partition.
__global__ __launch_bounds__(256) void k_stats(
    const void* __restrict__ xlen, const void* __restrict__ ylen) {
    int blk = blockIdx.x;
    int tid = threadIdx.x;
    __shared__ float red[8][32];

    if (blk < 256) {
        // ---- row stats ----
        int lane = tid & 31;
        int wid  = tid >> 5;
        int b = blk >> 6;
        int n = (blk & 63) * 8 + wid;
        int xl = load_len(xlen, b);
        int yl = load_len(ylen, b);
        if (n >= xl) return;

        const float*  zr = g_z + ((size_t)b * NN + n) * MM;
        const float4* z4 = (const float4*)zr;
        int nv4 = yl >> 2;
        int base = yl & ~3;

        float zmin = 3.0e38f;
#pragma unroll 4
        for (int i = lane; i < nv4; i += 32) {
            float4 v = z4[i];
            zmin = fminf(zmin, fminf(fminf(v.x, v.y), fminf(v.z, v.w)));
        }
        if (base + lane < yl) zmin = fminf(zmin, zr[base + lane]);
#pragma unroll
        for (int o = 16; o; o >>= 1) zmin = fminf(zmin, __shfl_xor_sync(0xffffffffu, zmin, o));

        float s = 0.0f;
#pragma unroll 4
        for (int i = lane; i < nv4; i += 32) {
            float4 v = z4[i];
            s += __expf(zmin - v.x) + __expf(zmin - v.y)
               + __expf(zmin - v.z) + __expf(zmin - v.w);
        }
        if (base + lane < yl) s += __expf(zmin - zr[base + lane]);
#pragma unroll
        for (int o = 16; o; o >>= 1) s += __shfl_xor_sync(0xffffffffu, s, o);

        if (lane == 0) {
            g_rmin[b * NN + n] = zmin;
            g_rinv[b * NN + n] = 1.0f / s;
        }
    } else {
        // ---- col stats ----
        int cblk = blk - 256;           // 0..63
        int b  = cblk >> 4;
        int m0 = (cblk & 15) * 32;
        int xl = load_len(xlen, b);
        int yl = load_len(ylen, b);
        if (m0 >= yl) return;

        int tx = tid & 31;
        int tg = tid >> 5;              // 0..7
        int m = m0 + tx;
        const float* zc = g_z + (size_t)b * NN * MM + m;

        float zmin = 3.0e38f;
        int n = tg;
        for (; n + 24 < xl; n += 32) {
            float a0 = zc[(size_t)(n     ) * MM];
            float a1 = zc[(size_t)(n +  8) * MM];
            float a2 = zc[(size_t)(n + 16) * MM];
            float a3 = zc[(size_t)(n + 24) * MM];
            zmin = fminf(zmin, fminf(fminf(a0, a1), fminf(a2, a3)));
        }
        for (; n < xl; n += 8) zmin = fminf(zmin, zc[(size_t)n * MM]);
        red[tg][tx] = zmin;
        __syncthreads();
        if (tg == 0) {
            float cm = red[0][tx];
#pragma unroll
            for (int r = 1; r < 8; r++) cm = fminf(cm, red[r][tx]);
            red[0][tx] = cm;
        }
        __syncthreads();
        float cm = red[0][tx];
        __syncthreads();

        float s = 0.0f;
        n = tg;
        for (; n + 24 < xl; n += 32) {
            float a0 = zc[(size_t)(n     ) * MM];
            float a1 = zc[(size_t)(n +  8) * MM];
            float a2 = zc[(size_t)(n + 16) * MM];
            float a3 = zc[(size_t)(n + 24) * MM];
            s += __expf(cm - a0) + __expf(cm - a1) + __expf(cm - a2) + __expf(cm - a3);
        }
        for (; n < xl; n += 8) s += __expf(cm - zc[(size_t)n * MM]);
        red[tg][tx] = s;
        __syncthreads();
        if (tg == 0) {
            float t = red[0][tx];
#pragma unroll
            for (int r = 1; r < 8; r++) t += red[r][tx];
            g_cmin[b * MM + m] = cm;
            g_cinv[b * MM + m] = 1.0f / t;
        }
    }
}

// ---------------- kernel 3: combine + fused final reduction --------------
// 256 blocks x 256 threads; 8 warps/block, one (b,n) row per warp.
// Last block per batch (deterministic counter) does the final reduce.
__global__ __launch_bounds__(256) void k_accum(
    const void* __restrict__ xlen, const void* __restrict__ ylen,
    float* __restrict__ out) {
    int blk = blockIdx.x;
    int tid = threadIdx.x;
    int lane = tid & 31;
    int wid  = tid >> 5;
    int b = blk >> 6;
    int n = (blk & 63) * 8 + wid;
    int xl = load_len(xlen, b);
    int yl = load_len(ylen, b);

    if (n < xl) {
        const float*  zr  = g_z + ((size_t)b * NN + n) * MM;
        const float4* z4  = (const float4*)zr;
        const float*  cmn = g_cmin + b * MM;
        const float*  civ = g_cinv + b * MM;
        const float4* cm4 = (const float4*)cmn;
        const float4* ci4 = (const float4*)civ;
        float rmin = g_rmin[b * NN + n];
        float rinv = g_rinv[b * NN + n];

        int nv4 = yl >> 2;
        int base = yl & ~3;

        float num = 0.0f, den = 0.0f;
#pragma unroll 2
        for (int i = lane; i < nv4; i += 32) {
            float4 z = z4[i];
            float4 cm = cm4[i];
            float4 ci = ci4[i];
            {
                float beta  = __expf(rmin - z.x) * rinv;
                float alpha = __expf(cm.x - z.x) * ci.x;
                float a = alpha + beta - alpha * beta;
                den += a; num += a * z.x;
            }
            {
                float beta  = __expf(rmin - z.y) * rinv;
                float alpha = __expf(cm.y - z.y) * ci.y;
                float a = alpha + beta - alpha * beta;
                den += a; num += a * z.y;
            }
            {
                float beta  = __expf(rmin - z.z) * rinv;
                float alpha = __expf(cm.z - z.z) * ci.z;
                float a = alpha + beta - alpha * beta;
                den += a; num += a * z.z;
            }
            {
                float beta  = __expf(rmin - z.w) * rinv;
                float alpha = __expf(cm.w - z.w) * ci.w;
                float a = alpha + beta - alpha * beta;
                den += a; num += a * z.w;
            }
        }
        if (base + lane < yl) {
            int m = base + lane;
            float z = zr[m];
            float beta  = __expf(rmin - z) * rinv;
            float alpha = __expf(cmn[m] - z) * civ[m];
            float a = alpha + beta - alpha * beta;
            den += a; num += a * z;
        }
#pragma unroll
        for (int o = 16; o; o >>= 1) {
            num += __shfl_xor_sync(0xffffffffu, num, o);
            den += __shfl_xor_sync(0xffffffffu, den, o);
        }
        if (lane == 0) {
            g_pnum[b * NN + n] = num;
            g_pden[b * NN + n] = den;
        }
    }

    // ---- last-block-done: fused final reduction (deterministic) ----
    __shared__ int s_last;
    __syncthreads();
    if (tid == 0) {
        __threadfence();
        int old = atomicAdd(&g_cnt[b], 1);
        s_last = (old == 63);
    }
    __syncthreads();
    if (!s_last) return;
    __threadfence();

    float num = 0.0f, den = 0.0f;
    for (int i = tid; i < xl; i += 256) {
        num += g_pnum[b * NN + i];
        den += g_pden[b * NN + i];
    }
    __shared__ float sn[256];
    __shared__ float sd[256];
    sn[tid] = num;
    sd[tid] = den;
    __syncthreads();
    for (int s2 = 128; s2; s2 >>= 1) {
        if (tid < s2) {
            sn[tid] += sn[tid + s2];
            sd[tid] += sd[tid + s2];
        }
        __syncthreads();
    }
    if (tid == 0) out[b] = -sn[0] / sd[0];
}

// ---------------- launch ----------------
extern "C" void kernel_launch(void* const* d_in, const int* in_sizes, int n_in,
                              void* d_out, int out_size) {
    const float* x = (const float*)d_in[0];
    const float* y = (const float*)d_in[1];
    const void* xl = d_in[2];
    const void* yl = d_in[3];
    float* out = (float*)d_out;

    dim3 g1(MM / TM, NN / TN, BB);          // (16, 8, 4) = 512 blocks
    k_zdiff<<<g1, 256>>>(x, y, xl, yl);
    k_stats<<<320, 256>>>(xl, yl);
    k_accum<<<256, 256>>>(xl, yl, out);
}